// round 15
// baseline (speedup 1.0000x reference)
#include <cuda_runtime.h>
#include <cuda.h>
#include <cuda_fp16.h>
#include <math.h>
#include <stdint.h>

#define BATCH 4
#define CH 256
#define NPOS 4096
#define KP 256                      // single-term fp16 K
#define EPS_NORM 2.220446049250313e-16f
#define EPS_MIN 1e-5f
#define INV_H 10.0f

#define TILE_M 128
#define TILE_N 256
#define KCHUNK 64
#define NCHUNK (KP / KCHUNK)        // 4
#define NSTAGE 4                    // == NCHUNK: fully prefetched, no ring
#define A_STAGE_BYTES (TILE_M * 128)
#define B_STAGE_BYTES (TILE_N * 128)
#define STAGE_BYTES (A_STAGE_BYTES + B_STAGE_BYTES)
#define SMEM_DYN (NSTAGE * STAGE_BYTES)              // 192 KB
#define NP_SMEM (4 * 64 * 65 * 4)                    // 66,560 B

// ---------------- scratch ----------------
__device__ __half g_A [(size_t)BATCH * NPOS * KP];          // 8 MB
__device__ __half g_Bp[(size_t)BATCH * NPOS * KP];          // 8 MB
__device__ __half g_S[(size_t)BATCH * NPOS * NPOS];         // 134 MB
__device__ float g_mu[BATCH * CH];
__device__ float g_rowmax[BATCH * NPOS];
__device__ float g_beta[BATCH * NPOS];
__device__ float g_gamma[BATCH * NPOS];
__device__ float g_colmax[BATCH * NPOS];

// ---------------- ptx helpers ----------------
__device__ __forceinline__ uint32_t smem_u32(const void* p) {
    uint32_t a;
    asm("{ .reg .u64 t; cvta.to.shared.u64 t, %1; cvt.u32.u64 %0, t; }" : "=r"(a) : "l"(p));
    return a;
}
__device__ __forceinline__ void mbar_init(uint32_t mbar, uint32_t cnt) {
    asm volatile("mbarrier.init.shared.b64 [%0], %1;" :: "r"(mbar), "r"(cnt) : "memory");
}
__device__ __forceinline__ void mbar_expect_tx(uint32_t mbar, uint32_t bytes) {
    asm volatile("mbarrier.arrive.expect_tx.shared.b64 _, [%0], %1;"
                 :: "r"(mbar), "r"(bytes) : "memory");
}
__device__ __forceinline__ void mbar_wait(uint32_t mbar, uint32_t parity) {
    asm volatile(
        "{\n\t.reg .pred P;\n\t"
        "WL_%=:\n\t"
        "mbarrier.try_wait.parity.acquire.cta.shared::cta.b64 P, [%0], %1, 0x989680;\n\t"
        "@P bra.uni WD_%=;\n\t"
        "bra.uni WL_%=;\n\t"
        "WD_%=:\n\t}"
        :: "r"(mbar), "r"(parity) : "memory");
}
__device__ __forceinline__ void tma_load_2d(uint32_t dst, const CUtensorMap* map,
                                            int cx, int cy, uint32_t mbar) {
    asm volatile(
        "cp.async.bulk.tensor.2d.shared::cta.global.tile.mbarrier::complete_tx::bytes "
        "[%0], [%1, {%2, %3}], [%4];"
        :: "r"(dst), "l"(map), "r"(cx), "r"(cy), "r"(mbar) : "memory");
}
__device__ __forceinline__ void ldm_x4(uint32_t* r, uint32_t addr) {
    asm volatile("ldmatrix.sync.aligned.m8n8.x4.shared.b16 {%0,%1,%2,%3}, [%4];"
                 : "=r"(r[0]), "=r"(r[1]), "=r"(r[2]), "=r"(r[3]) : "r"(addr));
}
__device__ __forceinline__ void mma_f16(float* d, const uint32_t* a, const uint32_t* b) {
    asm volatile(
        "mma.sync.aligned.m16n8k16.row.col.f32.f16.f16.f32 "
        "{%0,%1,%2,%3}, {%4,%5,%6,%7}, {%8,%9}, {%0,%1,%2,%3};"
        : "+f"(d[0]), "+f"(d[1]), "+f"(d[2]), "+f"(d[3])
        : "r"(a[0]), "r"(a[1]), "r"(a[2]), "r"(a[3]), "r"(b[0]), "r"(b[1]));
}

__device__ __forceinline__ void atomicMaxFloat(float* addr, float v) {
    if (v >= 0.0f) atomicMax((int*)addr, __float_as_int(v));
    else           atomicMin((unsigned int*)addr, __float_as_uint(v));
}
__device__ __forceinline__ float blockReduceSum(float v) {
    __shared__ float sh[32];
    int lane = threadIdx.x & 31, wid = threadIdx.x >> 5;
    #pragma unroll
    for (int o = 16; o; o >>= 1) v += __shfl_xor_sync(0xffffffffu, v, o);
    if (lane == 0) sh[wid] = v;
    __syncthreads();
    if (wid == 0) {
        int nw = (blockDim.x + 31) >> 5;
        v = (lane < nw) ? sh[lane] : 0.0f;
        #pragma unroll
        for (int o = 16; o; o >>= 1) v += __shfl_xor_sync(0xffffffffu, v, o);
    }
    return v;
}

// ---------------- kernel 1: per-(b,c) spatial mean of Y + fused init ----------------
__global__ __launch_bounds__(256) void k_mean(const float* __restrict__ Y) {
    int gtid = blockIdx.x * 256 + threadIdx.x;
    if (gtid < BATCH * NPOS) {
        g_rowmax[gtid] = -INFINITY;
        g_colmax[gtid] = -INFINITY;
    }
    size_t base = (size_t)blockIdx.x * NPOS;
    const float4* Y4 = (const float4*)(Y + base);
    float s = 0.0f;
    #pragma unroll
    for (int k = 0; k < 4; k++) {
        float4 v = Y4[threadIdx.x + k * 256];
        s += v.x + v.y + v.z + v.w;
    }
    s = blockReduceSum(s);
    if (threadIdx.x == 0) g_mu[blockIdx.x] = s * (1.0f / NPOS);
}

// ---------------- kernel 2: fused center+norm+fp16 pack (transpose) ----------------
__global__ __launch_bounds__(256) void k_normpack(const float* __restrict__ X,
                                                  const float* __restrict__ Y) {
    extern __shared__ float t[];                   // [4][64][65]
    __shared__ float partial[4][64];
    __shared__ float inv_s[64];
    int zb = blockIdx.z;
    int b = blockIdx.y, isY = zb & 1;
    const float* src = isY ? Y : X;
    __half* dstA = (isY ? g_Bp : g_A) + (size_t)b * NPOS * KP;
    int n0 = blockIdx.x * 64;
    int tx = threadIdx.x & 63, ty = threadIdx.x >> 6;   // ty 0..3

    #pragma unroll
    for (int cb = 0; cb < 4; cb++) {
        float* tc = t + cb * (64 * 65);
        #pragma unroll 4
        for (int r = 0; r < 16; r++) {
            int cl = ty + r * 4;
            int c = cb * 64 + cl;
            tc[cl * 65 + tx] = src[((size_t)(b * CH + c)) * NPOS + n0 + tx] - g_mu[b * CH + c];
        }
    }
    __syncthreads();
    {
        float s = 0.0f;
        const float* tq = t + ty * (64 * 65);
        #pragma unroll 8
        for (int c = 0; c < 64; c++) {
            float v = tq[c * 65 + tx];
            s = fmaf(v, v, s);
        }
        partial[ty][tx] = s;
    }
    __syncthreads();
    if (threadIdx.x < 64) {
        float s = partial[0][threadIdx.x] + partial[1][threadIdx.x]
                + partial[2][threadIdx.x] + partial[3][threadIdx.x];
        inv_s[threadIdx.x] = 1.0f / (sqrtf(s) + EPS_NORM);
    }
    __syncthreads();
    #pragma unroll
    for (int cb = 0; cb < 4; cb++) {
        const float* tc = t + cb * (64 * 65);
        #pragma unroll 4
        for (int r = 0; r < 16; r++) {
            int nl = ty + r * 4;
            int n = n0 + nl;
            float v = tc[tx * 65 + nl] * inv_s[nl];
            dstA[(size_t)n * KP + cb * 64 + tx] = __float2half(v);
        }
    }
}

// ---------------- kernel 3: mma.sync fp16 GEMM, register-pipelined (fixed addr) ----------------
__global__ __launch_bounds__(256, 1) void k_gemm_tc(
        const __grid_constant__ CUtensorMap tmA,
        const __grid_constant__ CUtensorMap tmB) {
    extern __shared__ __align__(1024) char smem[];
    __shared__ __align__(8) uint64_t mbar_s[NSTAGE];
    uint32_t stage0 = smem_u32(smem);
    uint32_t mb0 = smem_u32(mbar_s);

    int tid = threadIdx.x;
    int wid = tid >> 5, lane = tid & 31;
    int b = blockIdx.z;
    int i0 = blockIdx.y * TILE_M;
    int j0 = blockIdx.x * TILE_N;

    if (tid == 0) {
        #pragma unroll
        for (int s = 0; s < NSTAGE; s++) mbar_init(mb0 + 8 * s, 1);
    }
    __syncthreads();

    if (tid == 0) {
        #pragma unroll
        for (int p = 0; p < NSTAGE; p++) {             // all 4 K-chunks up front
            uint32_t full = mb0 + 8 * p;
            mbar_expect_tx(full, STAGE_BYTES);
            tma_load_2d(stage0 + p * STAGE_BYTES, &tmA, p * KCHUNK, b * NPOS + i0, full);
            tma_load_2d(stage0 + p * STAGE_BYTES + A_STAGE_BYTES, &tmB, p * KCHUNK,
                        b * NPOS + j0, full);
        }
    }

    int wm = wid & 1, wn = wid >> 1;                   // warp grid 2(m) x 4(n), tile 64x64
    float acc[4][8][4];
    #pragma unroll
    for (int mt = 0; mt < 4; mt++)
        #pragma unroll
        for (int nt = 0; nt < 8; nt++)
            #pragma unroll
            for (int r = 0; r < 4; r++) acc[mt][nt][r] = 0.0f;

    int rowA_l = (lane & 15);
    int hiA = lane >> 4;
    int rowB_l = (lane & 7) + ((lane >> 4) << 3);
    int hiB = (lane >> 3) & 1;

    // kk-invariant parts: base (pre-swizzle sum w/o kk term) and swizzle mask
    uint32_t aBase[4], aSw[4], bBase[4], bSw[4];
    #pragma unroll
    for (int mt = 0; mt < 4; mt++) {
        int row = wm * 64 + mt * 16 + rowA_l;
        aBase[mt] = (uint32_t)(row * 128) + hiA * 16;
        aSw[mt]   = (uint32_t)((row & 7) << 4);
    }
    #pragma unroll
    for (int p = 0; p < 4; p++) {
        int row = wn * 64 + p * 16 + rowB_l;
        bBase[p] = (uint32_t)(row * 128) + hiB * 16;
        bSw[p]   = (uint32_t)((row & 7) << 4);
    }

    // fragment double-buffer; all indices compile-time after full unroll
    uint32_t af[2][4][4], bf[2][4][4];
    // addr = stageOff(+A_STAGE for B) + ((base + kk*32) ^ sw)  -- XOR over FULL sum, in-bounds
    #define LOADF(buf, kcv, kkv)                                                      \
        do {                                                                          \
            uint32_t _ao = stage0 + (kcv) * STAGE_BYTES;                              \
            uint32_t _bo = _ao + A_STAGE_BYTES;                                       \
            _Pragma("unroll")                                                         \
            for (int _m = 0; _m < 4; _m++)                                            \
                ldm_x4(af[buf][_m], _ao + ((aBase[_m] + (kkv) * 32) ^ aSw[_m]));      \
            _Pragma("unroll")                                                         \
            for (int _p = 0; _p < 4; _p++)                                            \
                ldm_x4(bf[buf][_p], _bo + ((bBase[_p] + (kkv) * 32) ^ bSw[_p]));      \
        } while (0)

    mbar_wait(mb0, 0);
    LOADF(0, 0, 0);

    #pragma unroll
    for (int step = 0; step < NCHUNK * 4; step++) {
        const int cur = step & 1;
        if (step + 1 < NCHUNK * 4) {
            const int ns = step + 1, nkc = ns >> 2, nkk = ns & 3;
            if (nkk == 0) mbar_wait(mb0 + 8 * nkc, 0);
            LOADF(cur ^ 1, nkc, nkk);
        }
        #pragma unroll
        for (int mt = 0; mt < 4; mt++)
            #pragma unroll
            for (int nt = 0; nt < 8; nt++)
                mma_f16(acc[mt][nt], af[cur][mt], &bf[cur][nt >> 1][(nt & 1) * 2]);
    }
    #undef LOADF

    // -------- epilogue: direct fp16 stores + rowmax of the ROUNDED values --------
    __half* Sb = g_S + (size_t)b * NPOS * NPOS;
    int rbase = i0 + wm * 64;
    int cbase = j0 + wn * 64 + (lane & 3) * 2;
    #pragma unroll
    for (int mt = 0; mt < 4; mt++) {
        #pragma unroll
        for (int h = 0; h < 2; h++) {
            int r = rbase + mt * 16 + h * 8 + (lane >> 2);
            float m = -INFINITY;
            #pragma unroll
            for (int nt = 0; nt < 8; nt++) {
                __half2 hv = __floats2half2_rn(acc[mt][nt][h * 2], acc[mt][nt][h * 2 + 1]);
                float2 f = __half22float2(hv);
                m = fmaxf(m, fmaxf(f.x, f.y));
                *(__half2*)&Sb[(size_t)r * NPOS + cbase + nt * 8] = hv;
            }
            m = fmaxf(m, __shfl_xor_sync(0xffffffffu, m, 1));
            m = fmaxf(m, __shfl_xor_sync(0xffffffffu, m, 2));
            if ((lane & 3) == 0) atomicMaxFloat(&g_rowmax[b * NPOS + r], m);
        }
    }
}

// ---------------- kernel 4: per-row softmax denominator (batched loads) ----------------
__global__ __launch_bounds__(128) void k_rowsum() {
    int row = blockIdx.x;                   // b*NPOS + i
    int b = row >> 12, i = row & (NPOS - 1);
    float rmax = g_rowmax[row];
    float den  = (1.0f - rmax) + EPS_MIN;
    float beta  = INV_H / den;
    float alpha = INV_H - beta;
    const uint4* Sr = (const uint4*)(g_S + (size_t)b * NPOS * NPOS + (size_t)i * NPOS);
    uint4 u[4];
    #pragma unroll
    for (int k = 0; k < 4; k++) u[k] = Sr[threadIdx.x + k * 128];
    float sum = 0.0f;
    #pragma unroll
    for (int k = 0; k < 4; k++) {
        float2 f0 = __half22float2(*(__half2*)&u[k].x);
        float2 f1 = __half22float2(*(__half2*)&u[k].y);
        float2 f2 = __half22float2(*(__half2*)&u[k].z);
        float2 f3 = __half22float2(*(__half2*)&u[k].w);
        sum += __expf(fmaf(beta, f0.x, alpha)) + __expf(fmaf(beta, f0.y, alpha));
        sum += __expf(fmaf(beta, f1.x, alpha)) + __expf(fmaf(beta, f1.y, alpha));
        sum += __expf(fmaf(beta, f2.x, alpha)) + __expf(fmaf(beta, f2.y, alpha));
        sum += __expf(fmaf(beta, f3.x, alpha)) + __expf(fmaf(beta, f3.y, alpha));
    }
    sum = blockReduceSum(sum);
    if (threadIdx.x == 0) {
        g_beta[row]  = beta;
        g_gamma[row] = alpha - logf(sum);
    }
}

// ---------------- kernel 5: column max of (gamma_i + beta_i*S_ij), MLP=4 ----------------
#define ICHUNK 128
__global__ __launch_bounds__(256) void k_colmax() {
    int b = blockIdx.z;
    int jBase = blockIdx.x * 2048;          // 256 threads * 8 cols
    int iBase = blockIdx.y * ICHUNK;
    __shared__ float bs[ICHUNK], gs[ICHUNK];
    if (threadIdx.x < ICHUNK) {
        bs[threadIdx.x] = g_beta[b * NPOS + iBase + threadIdx.x];
        gs[threadIdx.x] = g_gamma[b * NPOS + iBase + threadIdx.x];
    }
    __syncthreads();
    const __half* Sb = g_S + (size_t)b * NPOS * NPOS;
    int j = jBase + threadIdx.x * 8;
    float m[8];
    #pragma unroll
    for (int q = 0; q < 8; q++) m[q] = -INFINITY;
    for (int ii = 0; ii < ICHUNK; ii += 4) {
        uint4 u[4];
        #pragma unroll
        for (int r = 0; r < 4; r++)
            u[r] = *(const uint4*)&Sb[(size_t)(iBase + ii + r) * NPOS + j];
        #pragma unroll
        for (int r = 0; r < 4; r++) {
            float be = bs[ii + r], ga = gs[ii + r];
            float2 f0 = __half22float2(*(__half2*)&u[r].x);
            float2 f1 = __half22float2(*(__half2*)&u[r].y);
            float2 f2 = __half22float2(*(__half2*)&u[r].z);
            float2 f3 = __half22float2(*(__half2*)&u[r].w);
            m[0] = fmaxf(m[0], fmaf(be, f0.x, ga));
            m[1] = fmaxf(m[1], fmaf(be, f0.y, ga));
            m[2] = fmaxf(m[2], fmaf(be, f1.x, ga));
            m[3] = fmaxf(m[3], fmaf(be, f1.y, ga));
            m[4] = fmaxf(m[4], fmaf(be, f2.x, ga));
            m[5] = fmaxf(m[5], fmaf(be, f2.y, ga));
            m[6] = fmaxf(m[6], fmaf(be, f3.x, ga));
            m[7] = fmaxf(m[7], fmaf(be, f3.y, ga));
        }
    }
    float* cm = g_colmax + b * NPOS + j;
    #pragma unroll
    for (int q = 0; q < 8; q++) atomicMaxFloat(cm + q, m[q]);
}

// ---------------- kernel 6: fused per-batch sum(exp(colmax)) + final output ----------------
__global__ __launch_bounds__(256) void k_cxfinal(float* __restrict__ out) {
    int b = blockIdx.x;
    const float* cm = g_colmax + b * NPOS;
    float s = 0.0f;
    #pragma unroll
    for (int k = 0; k < NPOS / 256; k++)
        s += __expf(cm[threadIdx.x + k * 256]);
    s = blockReduceSum(s);
    if (threadIdx.x == 0) out[b] = -logf(s * (1.0f / NPOS));
}

// ---------------- host: tensormap encode via driver entry point ----------------
typedef CUresult (CUDAAPI *PFN_encodeTiled)(
    CUtensorMap*, CUtensorMapDataType, cuuint32_t, void*,
    const cuuint64_t*, const cuuint64_t*, const cuuint32_t*, const cuuint32_t*,
    CUtensorMapInterleave, CUtensorMapSwizzle, CUtensorMapL2promotion, CUtensorMapFloatOOBfill);

static PFN_encodeTiled get_encoder() {
    static PFN_encodeTiled fn = nullptr;
    if (!fn) {
        cudaDriverEntryPointQueryResult st;
        cudaGetDriverEntryPoint("cuTensorMapEncodeTiled", (void**)&fn,
                                cudaEnableDefault, &st);
    }
    return fn;
}

static void make_map(CUtensorMap* tm, void* ptr, uint32_t boxRows) {
    cuuint64_t dims[2]    = {KP, (cuuint64_t)BATCH * NPOS};
    cuuint64_t strides[1] = {KP * 2};
    cuuint32_t box[2]     = {KCHUNK, boxRows};
    cuuint32_t es[2]      = {1, 1};
    get_encoder()(tm, CU_TENSOR_MAP_DATA_TYPE_FLOAT16, 2, ptr,
                  dims, strides, box, es,
                  CU_TENSOR_MAP_INTERLEAVE_NONE, CU_TENSOR_MAP_SWIZZLE_128B,
                  CU_TENSOR_MAP_L2_PROMOTION_L2_128B, CU_TENSOR_MAP_FLOAT_OOB_FILL_NONE);
}

// ---------------- launch ----------------
extern "C" void kernel_launch(void* const* d_in, const int* in_sizes, int n_in,
                              void* d_out, int out_size) {
    const float* X = (const float*)d_in[0];
    const float* Y = (const float*)d_in[1];
    float* out = (float*)d_out;

    void *pA, *pB;
    cudaGetSymbolAddress(&pA, g_A);
    cudaGetSymbolAddress(&pB, g_Bp);
    CUtensorMap tmA, tmB;
    make_map(&tmA, pA, TILE_M);
    make_map(&tmB, pB, TILE_N);

    cudaFuncSetAttribute(k_gemm_tc, cudaFuncAttributeMaxDynamicSharedMemorySize, SMEM_DYN);
    cudaFuncSetAttribute(k_normpack, cudaFuncAttributeMaxDynamicSharedMemorySize, NP_SMEM);

    k_mean<<<BATCH * CH, 256>>>(Y);
    k_normpack<<<dim3(NPOS / 64, BATCH, 2), 256, NP_SMEM>>>(X, Y);
    k_gemm_tc<<<dim3(NPOS / TILE_N, NPOS / TILE_M, BATCH), 256, SMEM_DYN>>>(tmA, tmB);
    k_rowsum<<<BATCH * NPOS, 128>>>();
    k_colmax<<<dim3(NPOS / 2048, NPOS / ICHUNK, BATCH), 256>>>();
    k_cxfinal<<<BATCH, 256>>>(out);
}

// round 16
// speedup vs baseline: 1.0057x; 1.0057x over previous
#include <cuda_runtime.h>
#include <cuda.h>
#include <cuda_fp16.h>
#include <math.h>
#include <stdint.h>

#define BATCH 4
#define CH 256
#define NPOS 4096
#define KP 256                      // single-term fp16 K
#define EPS_NORM 2.220446049250313e-16f
#define EPS_MIN 1e-5f
#define INV_H 10.0f

#define TILE_M 128
#define TILE_N 256
#define KCHUNK 64
#define NCHUNK (KP / KCHUNK)        // 4
#define NSTAGE 4                    // == NCHUNK: fully prefetched, no ring
#define A_STAGE_BYTES (TILE_M * 128)
#define B_STAGE_BYTES (TILE_N * 128)
#define STAGE_BYTES (A_STAGE_BYTES + B_STAGE_BYTES)
#define SMEM_DYN (NSTAGE * STAGE_BYTES)              // 192 KB
#define NP_SMEM (4 * 64 * 65 * 4)                    // 66,560 B

// ---------------- scratch ----------------
__device__ __half g_A [(size_t)BATCH * NPOS * KP];          // 8 MB
__device__ __half g_Bp[(size_t)BATCH * NPOS * KP];          // 8 MB
__device__ __half g_S[(size_t)BATCH * NPOS * NPOS];         // 134 MB
__device__ float g_mu[BATCH * CH];
__device__ float g_rowmax[BATCH * NPOS];
__device__ float2 g_bg[BATCH * NPOS];                       // (beta, gamma) packed
__device__ float g_colmax[BATCH * NPOS];

// ---------------- ptx helpers ----------------
__device__ __forceinline__ uint32_t smem_u32(const void* p) {
    uint32_t a;
    asm("{ .reg .u64 t; cvta.to.shared.u64 t, %1; cvt.u32.u64 %0, t; }" : "=r"(a) : "l"(p));
    return a;
}
__device__ __forceinline__ void mbar_init(uint32_t mbar, uint32_t cnt) {
    asm volatile("mbarrier.init.shared.b64 [%0], %1;" :: "r"(mbar), "r"(cnt) : "memory");
}
__device__ __forceinline__ void mbar_expect_tx(uint32_t mbar, uint32_t bytes) {
    asm volatile("mbarrier.arrive.expect_tx.shared.b64 _, [%0], %1;"
                 :: "r"(mbar), "r"(bytes) : "memory");
}
__device__ __forceinline__ void mbar_wait(uint32_t mbar, uint32_t parity) {
    asm volatile(
        "{\n\t.reg .pred P;\n\t"
        "WL_%=:\n\t"
        "mbarrier.try_wait.parity.acquire.cta.shared::cta.b64 P, [%0], %1, 0x989680;\n\t"
        "@P bra.uni WD_%=;\n\t"
        "bra.uni WL_%=;\n\t"
        "WD_%=:\n\t}"
        :: "r"(mbar), "r"(parity) : "memory");
}
__device__ __forceinline__ void tma_load_2d(uint32_t dst, const CUtensorMap* map,
                                            int cx, int cy, uint32_t mbar) {
    asm volatile(
        "cp.async.bulk.tensor.2d.shared::cta.global.tile.mbarrier::complete_tx::bytes "
        "[%0], [%1, {%2, %3}], [%4];"
        :: "r"(dst), "l"(map), "r"(cx), "r"(cy), "r"(mbar) : "memory");
}
__device__ __forceinline__ void ldm_x4(uint32_t* r, uint32_t addr) {
    asm volatile("ldmatrix.sync.aligned.m8n8.x4.shared.b16 {%0,%1,%2,%3}, [%4];"
                 : "=r"(r[0]), "=r"(r[1]), "=r"(r[2]), "=r"(r[3]) : "r"(addr));
}
__device__ __forceinline__ void mma_f16(float* d, const uint32_t* a, const uint32_t* b) {
    asm volatile(
        "mma.sync.aligned.m16n8k16.row.col.f32.f16.f16.f32 "
        "{%0,%1,%2,%3}, {%4,%5,%6,%7}, {%8,%9}, {%0,%1,%2,%3};"
        : "+f"(d[0]), "+f"(d[1]), "+f"(d[2]), "+f"(d[3])
        : "r"(a[0]), "r"(a[1]), "r"(a[2]), "r"(a[3]), "r"(b[0]), "r"(b[1]));
}

__device__ __forceinline__ void atomicMaxFloat(float* addr, float v) {
    if (v >= 0.0f) atomicMax((int*)addr, __float_as_int(v));
    else           atomicMin((unsigned int*)addr, __float_as_uint(v));
}
__device__ __forceinline__ float blockReduceSum(float v) {
    __shared__ float sh[32];
    int lane = threadIdx.x & 31, wid = threadIdx.x >> 5;
    #pragma unroll
    for (int o = 16; o; o >>= 1) v += __shfl_xor_sync(0xffffffffu, v, o);
    if (lane == 0) sh[wid] = v;
    __syncthreads();
    if (wid == 0) {
        int nw = (blockDim.x + 31) >> 5;
        v = (lane < nw) ? sh[lane] : 0.0f;
        #pragma unroll
        for (int o = 16; o; o >>= 1) v += __shfl_xor_sync(0xffffffffu, v, o);
    }
    return v;
}

// ---------------- kernel 1: per-(b,c) spatial mean of Y + fused init ----------------
__global__ __launch_bounds__(256) void k_mean(const float* __restrict__ Y) {
    int gtid = blockIdx.x * 256 + threadIdx.x;
    if (gtid < BATCH * NPOS) {
        g_rowmax[gtid] = -INFINITY;
        g_colmax[gtid] = -INFINITY;
    }
    size_t base = (size_t)blockIdx.x * NPOS;
    const float4* Y4 = (const float4*)(Y + base);
    float s = 0.0f;
    #pragma unroll
    for (int k = 0; k < 4; k++) {
        float4 v = Y4[threadIdx.x + k * 256];
        s += v.x + v.y + v.z + v.w;
    }
    s = blockReduceSum(s);
    if (threadIdx.x == 0) g_mu[blockIdx.x] = s * (1.0f / NPOS);
}

// ---------------- kernel 2: fused center+norm+fp16 pack (transpose) ----------------
__global__ __launch_bounds__(256) void k_normpack(const float* __restrict__ X,
                                                  const float* __restrict__ Y) {
    extern __shared__ float t[];                   // [4][64][65]
    __shared__ float partial[4][64];
    __shared__ float inv_s[64];
    int zb = blockIdx.z;
    int b = blockIdx.y, isY = zb & 1;
    const float* src = isY ? Y : X;
    __half* dstA = (isY ? g_Bp : g_A) + (size_t)b * NPOS * KP;
    int n0 = blockIdx.x * 64;
    int tx = threadIdx.x & 63, ty = threadIdx.x >> 6;   // ty 0..3

    #pragma unroll
    for (int cb = 0; cb < 4; cb++) {
        float* tc = t + cb * (64 * 65);
        #pragma unroll 4
        for (int r = 0; r < 16; r++) {
            int cl = ty + r * 4;
            int c = cb * 64 + cl;
            tc[cl * 65 + tx] = src[((size_t)(b * CH + c)) * NPOS + n0 + tx] - g_mu[b * CH + c];
        }
    }
    __syncthreads();
    {
        float s = 0.0f;
        const float* tq = t + ty * (64 * 65);
        #pragma unroll 8
        for (int c = 0; c < 64; c++) {
            float v = tq[c * 65 + tx];
            s = fmaf(v, v, s);
        }
        partial[ty][tx] = s;
    }
    __syncthreads();
    if (threadIdx.x < 64) {
        float s = partial[0][threadIdx.x] + partial[1][threadIdx.x]
                + partial[2][threadIdx.x] + partial[3][threadIdx.x];
        inv_s[threadIdx.x] = 1.0f / (sqrtf(s) + EPS_NORM);
    }
    __syncthreads();
    #pragma unroll
    for (int cb = 0; cb < 4; cb++) {
        const float* tc = t + cb * (64 * 65);
        #pragma unroll 4
        for (int r = 0; r < 16; r++) {
            int nl = ty + r * 4;
            int n = n0 + nl;
            float v = tc[tx * 65 + nl] * inv_s[nl];
            dstA[(size_t)n * KP + cb * 64 + tx] = __float2half(v);
        }
    }
}

// ---------------- kernel 3: mma.sync fp16 GEMM (K=256 fully prefetched) ----------------
__global__ __launch_bounds__(256, 1) void k_gemm_tc(
        const __grid_constant__ CUtensorMap tmA,
        const __grid_constant__ CUtensorMap tmB) {
    extern __shared__ __align__(1024) char smem[];
    __shared__ __align__(8) uint64_t mbar_s[NSTAGE];
    uint32_t stage0 = smem_u32(smem);
    uint32_t mb0 = smem_u32(mbar_s);

    int tid = threadIdx.x;
    int wid = tid >> 5, lane = tid & 31;
    int b = blockIdx.z;
    int i0 = blockIdx.y * TILE_M;
    int j0 = blockIdx.x * TILE_N;

    if (tid == 0) {
        #pragma unroll
        for (int s = 0; s < NSTAGE; s++) mbar_init(mb0 + 8 * s, 1);
    }
    __syncthreads();

    if (tid == 0) {
        #pragma unroll
        for (int p = 0; p < NSTAGE; p++) {             // all 4 K-chunks up front
            uint32_t full = mb0 + 8 * p;
            mbar_expect_tx(full, STAGE_BYTES);
            tma_load_2d(stage0 + p * STAGE_BYTES, &tmA, p * KCHUNK, b * NPOS + i0, full);
            tma_load_2d(stage0 + p * STAGE_BYTES + A_STAGE_BYTES, &tmB, p * KCHUNK,
                        b * NPOS + j0, full);
        }
    }

    int wm = wid & 1, wn = wid >> 1;                   // warp grid 2(m) x 4(n), tile 64x64
    float acc[4][8][4];
    #pragma unroll
    for (int mt = 0; mt < 4; mt++)
        #pragma unroll
        for (int nt = 0; nt < 8; nt++)
            #pragma unroll
            for (int r = 0; r < 4; r++) acc[mt][nt][r] = 0.0f;

    int rowA_l = (lane & 15);
    int hiA = lane >> 4;
    int rowB_l = (lane & 7) + ((lane >> 4) << 3);
    int hiB = (lane >> 3) & 1;

    #pragma unroll
    for (int kc = 0; kc < NCHUNK; kc++) {
        mbar_wait(mb0 + 8 * kc, 0);

        uint32_t aOff = stage0 + kc * STAGE_BYTES;
        uint32_t bOff = aOff + A_STAGE_BYTES;
        #pragma unroll
        for (int kk = 0; kk < 4; kk++) {
            uint32_t a[4][4], br[4][4];
            #pragma unroll
            for (int mt = 0; mt < 4; mt++) {
                int row = wm * 64 + mt * 16 + rowA_l;
                uint32_t off = (uint32_t)(row * 128 + kk * 32);
                off = (off + hiA * 16) ^ ((row & 7) << 4);
                ldm_x4(a[mt], aOff + off);
            }
            #pragma unroll
            for (int p = 0; p < 4; p++) {
                int row = wn * 64 + p * 16 + rowB_l;
                uint32_t off = (uint32_t)(row * 128 + kk * 32);
                off = (off + hiB * 16) ^ ((row & 7) << 4);
                ldm_x4(br[p], bOff + off);
            }
            #pragma unroll
            for (int mt = 0; mt < 4; mt++)
                #pragma unroll
                for (int nt = 0; nt < 8; nt++)
                    mma_f16(acc[mt][nt], a[mt], &br[nt >> 1][(nt & 1) * 2]);
        }
    }

    // -------- epilogue: direct fp16 stores + rowmax of the ROUNDED values --------
    __half* Sb = g_S + (size_t)b * NPOS * NPOS;
    int rbase = i0 + wm * 64;
    int cbase = j0 + wn * 64 + (lane & 3) * 2;
    #pragma unroll
    for (int mt = 0; mt < 4; mt++) {
        #pragma unroll
        for (int h = 0; h < 2; h++) {
            int r = rbase + mt * 16 + h * 8 + (lane >> 2);
            float m = -INFINITY;
            #pragma unroll
            for (int nt = 0; nt < 8; nt++) {
                __half2 hv = __floats2half2_rn(acc[mt][nt][h * 2], acc[mt][nt][h * 2 + 1]);
                float2 f = __half22float2(hv);
                m = fmaxf(m, fmaxf(f.x, f.y));
                *(__half2*)&Sb[(size_t)r * NPOS + cbase + nt * 8] = hv;
            }
            m = fmaxf(m, __shfl_xor_sync(0xffffffffu, m, 1));
            m = fmaxf(m, __shfl_xor_sync(0xffffffffu, m, 2));
            if ((lane & 3) == 0) atomicMaxFloat(&g_rowmax[b * NPOS + r], m);
        }
    }
}

// ---------------- kernel 4: per-row softmax denominator (2 rows per CTA) ----------------
__global__ __launch_bounds__(256) void k_rowsum() {
    int half = threadIdx.x >> 7;            // 0/1: which row of the pair
    int t = threadIdx.x & 127;
    int row = blockIdx.x * 2 + half;        // b*NPOS + i
    int b = row >> 12, i = row & (NPOS - 1);
    float rmax = g_rowmax[row];
    float den  = (1.0f - rmax) + EPS_MIN;
    float beta  = INV_H / den;
    float alpha = INV_H - beta;
    const uint4* Sr = (const uint4*)(g_S + (size_t)b * NPOS * NPOS + (size_t)i * NPOS);
    uint4 u[4];
    #pragma unroll
    for (int k = 0; k < 4; k++) u[k] = Sr[t + k * 128];
    float sum = 0.0f;
    #pragma unroll
    for (int k = 0; k < 4; k++) {
        float2 f0 = __half22float2(*(__half2*)&u[k].x);
        float2 f1 = __half22float2(*(__half2*)&u[k].y);
        float2 f2 = __half22float2(*(__half2*)&u[k].z);
        float2 f3 = __half22float2(*(__half2*)&u[k].w);
        sum += __expf(fmaf(beta, f0.x, alpha)) + __expf(fmaf(beta, f0.y, alpha));
        sum += __expf(fmaf(beta, f1.x, alpha)) + __expf(fmaf(beta, f1.y, alpha));
        sum += __expf(fmaf(beta, f2.x, alpha)) + __expf(fmaf(beta, f2.y, alpha));
        sum += __expf(fmaf(beta, f3.x, alpha)) + __expf(fmaf(beta, f3.y, alpha));
    }
    // reduce within each 128-thread half (4 warps)
    __shared__ float sh[2][4];
    int lane = t & 31, w = t >> 5;
    #pragma unroll
    for (int o = 16; o; o >>= 1) sum += __shfl_xor_sync(0xffffffffu, sum, o);
    if (lane == 0) sh[half][w] = sum;
    __syncthreads();
    if (t == 0) {
        float s = sh[half][0] + sh[half][1] + sh[half][2] + sh[half][3];
        g_bg[row] = make_float2(beta, alpha - logf(s));
    }
}

// ---------------- kernel 5: column max of (gamma_i + beta_i*S_ij), MLP=4 ----------------
#define ICHUNK 128
__global__ __launch_bounds__(256) void k_colmax() {
    int b = blockIdx.z;
    int jBase = blockIdx.x * 2048;          // 256 threads * 8 cols
    int iBase = blockIdx.y * ICHUNK;
    __shared__ float2 bg[ICHUNK];
    if (threadIdx.x < ICHUNK)
        bg[threadIdx.x] = g_bg[b * NPOS + iBase + threadIdx.x];
    __syncthreads();
    const __half* Sb = g_S + (size_t)b * NPOS * NPOS;
    int j = jBase + threadIdx.x * 8;
    float m[8];
    #pragma unroll
    for (int q = 0; q < 8; q++) m[q] = -INFINITY;
    for (int ii = 0; ii < ICHUNK; ii += 4) {
        uint4 u[4];
        #pragma unroll
        for (int r = 0; r < 4; r++)
            u[r] = *(const uint4*)&Sb[(size_t)(iBase + ii + r) * NPOS + j];
        #pragma unroll
        for (int r = 0; r < 4; r++) {
            float2 be_ga = bg[ii + r];
            float be = be_ga.x, ga = be_ga.y;
            float2 f0 = __half22float2(*(__half2*)&u[r].x);
            float2 f1 = __half22float2(*(__half2*)&u[r].y);
            float2 f2 = __half22float2(*(__half2*)&u[r].z);
            float2 f3 = __half22float2(*(__half2*)&u[r].w);
            m[0] = fmaxf(m[0], fmaf(be, f0.x, ga));
            m[1] = fmaxf(m[1], fmaf(be, f0.y, ga));
            m[2] = fmaxf(m[2], fmaf(be, f1.x, ga));
            m[3] = fmaxf(m[3], fmaf(be, f1.y, ga));
            m[4] = fmaxf(m[4], fmaf(be, f2.x, ga));
            m[5] = fmaxf(m[5], fmaf(be, f2.y, ga));
            m[6] = fmaxf(m[6], fmaf(be, f3.x, ga));
            m[7] = fmaxf(m[7], fmaf(be, f3.y, ga));
        }
    }
    float* cm = g_colmax + b * NPOS + j;
    #pragma unroll
    for (int q = 0; q < 8; q++) atomicMaxFloat(cm + q, m[q]);
}

// ---------------- kernel 6: fused per-batch sum(exp(colmax)) + final output ----------------
__global__ __launch_bounds__(256) void k_cxfinal(float* __restrict__ out) {
    int b = blockIdx.x;
    const float* cm = g_colmax + b * NPOS;
    float s = 0.0f;
    #pragma unroll
    for (int k = 0; k < NPOS / 256; k++)
        s += __expf(cm[threadIdx.x + k * 256]);
    s = blockReduceSum(s);
    if (threadIdx.x == 0) out[b] = -logf(s * (1.0f / NPOS));
}

// ---------------- host: tensormap encode via driver entry point ----------------
typedef CUresult (CUDAAPI *PFN_encodeTiled)(
    CUtensorMap*, CUtensorMapDataType, cuuint32_t, void*,
    const cuuint64_t*, const cuuint64_t*, const cuuint32_t*, const cuuint32_t*,
    CUtensorMapInterleave, CUtensorMapSwizzle, CUtensorMapL2promotion, CUtensorMapFloatOOBfill);

static PFN_encodeTiled get_encoder() {
    static PFN_encodeTiled fn = nullptr;
    if (!fn) {
        cudaDriverEntryPointQueryResult st;
        cudaGetDriverEntryPoint("cuTensorMapEncodeTiled", (void**)&fn,
                                cudaEnableDefault, &st);
    }
    return fn;
}

static void make_map(CUtensorMap* tm, void* ptr, uint32_t boxRows) {
    cuuint64_t dims[2]    = {KP, (cuuint64_t)BATCH * NPOS};
    cuuint64_t strides[1] = {KP * 2};
    cuuint32_t box[2]     = {KCHUNK, boxRows};
    cuuint32_t es[2]      = {1, 1};
    get_encoder()(tm, CU_TENSOR_MAP_DATA_TYPE_FLOAT16, 2, ptr,
                  dims, strides, box, es,
                  CU_TENSOR_MAP_INTERLEAVE_NONE, CU_TENSOR_MAP_SWIZZLE_128B,
                  CU_TENSOR_MAP_L2_PROMOTION_L2_128B, CU_TENSOR_MAP_FLOAT_OOB_FILL_NONE);
}

// ---------------- launch ----------------
extern "C" void kernel_launch(void* const* d_in, const int* in_sizes, int n_in,
                              void* d_out, int out_size) {
    const float* X = (const float*)d_in[0];
    const float* Y = (const float*)d_in[1];
    float* out = (float*)d_out;

    void *pA, *pB;
    cudaGetSymbolAddress(&pA, g_A);
    cudaGetSymbolAddress(&pB, g_Bp);
    CUtensorMap tmA, tmB;
    make_map(&tmA, pA, TILE_M);
    make_map(&tmB, pB, TILE_N);

    cudaFuncSetAttribute(k_gemm_tc, cudaFuncAttributeMaxDynamicSharedMemorySize, SMEM_DYN);
    cudaFuncSetAttribute(k_normpack, cudaFuncAttributeMaxDynamicSharedMemorySize, NP_SMEM);

    k_mean<<<BATCH * CH, 256>>>(Y);
    k_normpack<<<dim3(NPOS / 64, BATCH, 2), 256, NP_SMEM>>>(X, Y);
    k_gemm_tc<<<dim3(NPOS / TILE_N, NPOS / TILE_M, BATCH), 256, SMEM_DYN>>>(tmA, tmB);
    k_rowsum<<<BATCH * NPOS / 2, 256>>>();
    k_colmax<<<dim3(NPOS / 2048, NPOS / ICHUNK, BATCH), 256>>>();
    k_cxfinal<<<BATCH, 256>>>(out);
}

// round 17
// speedup vs baseline: 1.1058x; 1.0996x over previous
#include <cuda_runtime.h>
#include <cuda.h>
#include <cuda_fp16.h>
#include <math.h>
#include <stdint.h>

#define BATCH 4
#define CH 256
#define NPOS 4096
#define KP 256                      // single-term fp16 K
#define EPS_NORM 2.220446049250313e-16f
#define EPS_MIN 1e-5f
#define INV_H 10.0f

#define TILE_M 128
#define TILE_N 256
#define KCHUNK 64
#define NCHUNK (KP / KCHUNK)        // 4
#define NSTAGE 4                    // ring stages == chunks per tile (stage = kc)
#define NT (16 * 32 * BATCH)        // 2048 tiles
#define A_STAGE_BYTES (TILE_M * 128)
#define B_STAGE_BYTES (TILE_N * 128)
#define STAGE_BYTES (A_STAGE_BYTES + B_STAGE_BYTES)
#define SMEM_DYN (NSTAGE * STAGE_BYTES)              // 192 KB
#define NP_SMEM (4 * 64 * 65 * 4)                    // 66,560 B

// ---------------- scratch ----------------
__device__ __half g_A [(size_t)BATCH * NPOS * KP];          // 8 MB
__device__ __half g_Bp[(size_t)BATCH * NPOS * KP];          // 8 MB
__device__ __half g_S[(size_t)BATCH * NPOS * NPOS];         // 134 MB
__device__ float g_mu[BATCH * CH];
__device__ float g_rowmax[BATCH * NPOS];
__device__ float2 g_bg[BATCH * NPOS];                       // (beta, gamma) packed
__device__ float g_colmax[BATCH * NPOS];

// ---------------- ptx helpers ----------------
__device__ __forceinline__ uint32_t smem_u32(const void* p) {
    uint32_t a;
    asm("{ .reg .u64 t; cvta.to.shared.u64 t, %1; cvt.u32.u64 %0, t; }" : "=r"(a) : "l"(p));
    return a;
}
__device__ __forceinline__ void mbar_init(uint32_t mbar, uint32_t cnt) {
    asm volatile("mbarrier.init.shared.b64 [%0], %1;" :: "r"(mbar), "r"(cnt) : "memory");
}
__device__ __forceinline__ void mbar_expect_tx(uint32_t mbar, uint32_t bytes) {
    asm volatile("mbarrier.arrive.expect_tx.shared.b64 _, [%0], %1;"
                 :: "r"(mbar), "r"(bytes) : "memory");
}
__device__ __forceinline__ void mbar_arrive(uint32_t mbar) {
    asm volatile("mbarrier.arrive.shared.b64 _, [%0];" :: "r"(mbar) : "memory");
}
__device__ __forceinline__ void mbar_wait(uint32_t mbar, uint32_t parity) {
    asm volatile(
        "{\n\t.reg .pred P;\n\t"
        "WL_%=:\n\t"
        "mbarrier.try_wait.parity.acquire.cta.shared::cta.b64 P, [%0], %1, 0x989680;\n\t"
        "@P bra.uni WD_%=;\n\t"
        "bra.uni WL_%=;\n\t"
        "WD_%=:\n\t}"
        :: "r"(mbar), "r"(parity) : "memory");
}
__device__ __forceinline__ void tma_load_2d(uint32_t dst, const CUtensorMap* map,
                                            int cx, int cy, uint32_t mbar) {
    asm volatile(
        "cp.async.bulk.tensor.2d.shared::cta.global.tile.mbarrier::complete_tx::bytes "
        "[%0], [%1, {%2, %3}], [%4];"
        :: "r"(dst), "l"(map), "r"(cx), "r"(cy), "r"(mbar) : "memory");
}
__device__ __forceinline__ void ldm_x4(uint32_t* r, uint32_t addr) {
    asm volatile("ldmatrix.sync.aligned.m8n8.x4.shared.b16 {%0,%1,%2,%3}, [%4];"
                 : "=r"(r[0]), "=r"(r[1]), "=r"(r[2]), "=r"(r[3]) : "r"(addr));
}
__device__ __forceinline__ void mma_f16(float* d, const uint32_t* a, const uint32_t* b) {
    asm volatile(
        "mma.sync.aligned.m16n8k16.row.col.f32.f16.f16.f32 "
        "{%0,%1,%2,%3}, {%4,%5,%6,%7}, {%8,%9}, {%0,%1,%2,%3};"
        : "+f"(d[0]), "+f"(d[1]), "+f"(d[2]), "+f"(d[3])
        : "r"(a[0]), "r"(a[1]), "r"(a[2]), "r"(a[3]), "r"(b[0]), "r"(b[1]));
}

__device__ __forceinline__ void atomicMaxFloat(float* addr, float v) {
    if (v >= 0.0f) atomicMax((int*)addr, __float_as_int(v));
    else           atomicMin((unsigned int*)addr, __float_as_uint(v));
}
__device__ __forceinline__ float blockReduceSum(float v) {
    __shared__ float sh[32];
    int lane = threadIdx.x & 31, wid = threadIdx.x >> 5;
    #pragma unroll
    for (int o = 16; o; o >>= 1) v += __shfl_xor_sync(0xffffffffu, v, o);
    if (lane == 0) sh[wid] = v;
    __syncthreads();
    if (wid == 0) {
        int nw = (blockDim.x + 31) >> 5;
        v = (lane < nw) ? sh[lane] : 0.0f;
        #pragma unroll
        for (int o = 16; o; o >>= 1) v += __shfl_xor_sync(0xffffffffu, v, o);
    }
    return v;
}

// ---------------- kernel 1: per-(b,c) spatial mean of Y + fused init ----------------
__global__ __launch_bounds__(256) void k_mean(const float* __restrict__ Y) {
    int gtid = blockIdx.x * 256 + threadIdx.x;
    if (gtid < BATCH * NPOS) {
        g_rowmax[gtid] = -INFINITY;
        g_colmax[gtid] = -INFINITY;
    }
    size_t base = (size_t)blockIdx.x * NPOS;
    const float4* Y4 = (const float4*)(Y + base);
    float s = 0.0f;
    #pragma unroll
    for (int k = 0; k < 4; k++) {
        float4 v = Y4[threadIdx.x + k * 256];
        s += v.x + v.y + v.z + v.w;
    }
    s = blockReduceSum(s);
    if (threadIdx.x == 0) g_mu[blockIdx.x] = s * (1.0f / NPOS);
}

// ---------------- kernel 2: fused center+norm+fp16 pack (transpose) ----------------
__global__ __launch_bounds__(256) void k_normpack(const float* __restrict__ X,
                                                  const float* __restrict__ Y) {
    extern __shared__ float t[];                   // [4][64][65]
    __shared__ float partial[4][64];
    __shared__ float inv_s[64];
    int zb = blockIdx.z;
    int b = blockIdx.y, isY = zb & 1;
    const float* src = isY ? Y : X;
    __half* dstA = (isY ? g_Bp : g_A) + (size_t)b * NPOS * KP;
    int n0 = blockIdx.x * 64;
    int tx = threadIdx.x & 63, ty = threadIdx.x >> 6;   // ty 0..3

    #pragma unroll
    for (int cb = 0; cb < 4; cb++) {
        float* tc = t + cb * (64 * 65);
        #pragma unroll 4
        for (int r = 0; r < 16; r++) {
            int cl = ty + r * 4;
            int c = cb * 64 + cl;
            tc[cl * 65 + tx] = src[((size_t)(b * CH + c)) * NPOS + n0 + tx] - g_mu[b * CH + c];
        }
    }
    __syncthreads();
    {
        float s = 0.0f;
        const float* tq = t + ty * (64 * 65);
        #pragma unroll 8
        for (int c = 0; c < 64; c++) {
            float v = tq[c * 65 + tx];
            s = fmaf(v, v, s);
        }
        partial[ty][tx] = s;
    }
    __syncthreads();
    if (threadIdx.x < 64) {
        float s = partial[0][threadIdx.x] + partial[1][threadIdx.x]
                + partial[2][threadIdx.x] + partial[3][threadIdx.x];
        inv_s[threadIdx.x] = 1.0f / (sqrtf(s) + EPS_NORM);
    }
    __syncthreads();
    #pragma unroll
    for (int cb = 0; cb < 4; cb++) {
        const float* tc = t + cb * (64 * 65);
        #pragma unroll 4
        for (int r = 0; r < 16; r++) {
            int nl = ty + r * 4;
            int n = n0 + nl;
            float v = tc[tx * 65 + nl] * inv_s[nl];
            dstA[(size_t)n * KP + cb * 64 + tx] = __float2half(v);
        }
    }
}

// ---------------- kernel 3: persistent mma.sync fp16 GEMM (ring across tiles) ----------------
__global__ __launch_bounds__(256, 1) void k_gemm_tc(
        const __grid_constant__ CUtensorMap tmA,
        const __grid_constant__ CUtensorMap tmB,
        int ncta) {
    extern __shared__ __align__(1024) char smem[];
    __shared__ __align__(8) uint64_t mbar_s[2 * NSTAGE];
    uint32_t stage0 = smem_u32(smem);
    uint32_t mb0 = smem_u32(mbar_s);
    #define FULLB(s)  (mb0 + 8 * (s))
    #define EMPTYB(s) (mb0 + 8 * (NSTAGE + (s)))

    int tid = threadIdx.x;
    int wid = tid >> 5, lane = tid & 31;

    // local tile count for this CTA (static stride distribution)
    int ntl = (NT - (int)blockIdx.x + ncta - 1) / ncta;
    int total_gc = ntl * 4;

    if (tid == 0) {
        #pragma unroll
        for (int s = 0; s < NSTAGE; s++) {
            mbar_init(FULLB(s), 1);
            mbar_init(EMPTYB(s), 8);
        }
    }
    __syncthreads();

    // producer: issue chunk gcp (stage = gcp&3 = kc) of this CTA's tile stream
    #define ISSUE(gcp)                                                           \
        do {                                                                     \
            int _n = (gcp) >> 2, _kc = (gcp) & 3;                                \
            int _tile = (int)blockIdx.x + _n * ncta;                             \
            int _tx = _tile & 15, _ty = (_tile >> 4) & 31, _b = _tile >> 9;      \
            if ((gcp) >= NSTAGE) mbar_wait(EMPTYB(_kc), (_n - 1) & 1);           \
            mbar_expect_tx(FULLB(_kc), STAGE_BYTES);                             \
            tma_load_2d(stage0 + _kc * STAGE_BYTES, &tmA, _kc * KCHUNK,          \
                        _b * NPOS + _ty * TILE_M, FULLB(_kc));                   \
            tma_load_2d(stage0 + _kc * STAGE_BYTES + A_STAGE_BYTES, &tmB,        \
                        _kc * KCHUNK, _b * NPOS + _tx * TILE_N, FULLB(_kc));     \
        } while (0)

    if (tid == 0) {
        #pragma unroll
        for (int p = 0; p < NSTAGE - 1; p++)
            if (p < total_gc) ISSUE(p);
    }

    int wm = wid & 1, wn = wid >> 1;                   // warp grid 2(m) x 4(n), tile 64x64
    int rowA_l = (lane & 15);
    int hiA = lane >> 4;
    int rowB_l = (lane & 7) + ((lane >> 4) << 3);
    int hiB = (lane >> 3) & 1;

    for (int n = 0; n < ntl; n++) {
        int tile = (int)blockIdx.x + n * ncta;
        int ttx = tile & 15, tty = (tile >> 4) & 31, b = tile >> 9;
        int i0 = tty * TILE_M, j0 = ttx * TILE_N;

        float acc[4][8][4];
        #pragma unroll
        for (int mt = 0; mt < 4; mt++)
            #pragma unroll
            for (int nt = 0; nt < 8; nt++)
                #pragma unroll
                for (int r = 0; r < 4; r++) acc[mt][nt][r] = 0.0f;

        #pragma unroll
        for (int kc = 0; kc < NCHUNK; kc++) {
            int gc = n * 4 + kc;
            if (tid == 0 && gc + NSTAGE - 1 < total_gc) ISSUE(gc + NSTAGE - 1);
            mbar_wait(FULLB(kc), n & 1);

            uint32_t aOff = stage0 + kc * STAGE_BYTES;
            uint32_t bOff = aOff + A_STAGE_BYTES;
            #pragma unroll
            for (int kk = 0; kk < 4; kk++) {
                uint32_t a[4][4], br[4][4];
                #pragma unroll
                for (int mt = 0; mt < 4; mt++) {
                    int row = wm * 64 + mt * 16 + rowA_l;
                    uint32_t off = (uint32_t)(row * 128 + kk * 32);
                    off = (off + hiA * 16) ^ ((row & 7) << 4);
                    ldm_x4(a[mt], aOff + off);
                }
                #pragma unroll
                for (int p = 0; p < 4; p++) {
                    int row = wn * 64 + p * 16 + rowB_l;
                    uint32_t off = (uint32_t)(row * 128 + kk * 32);
                    off = (off + hiB * 16) ^ ((row & 7) << 4);
                    ldm_x4(br[p], bOff + off);
                }
                #pragma unroll
                for (int mt = 0; mt < 4; mt++)
                    #pragma unroll
                    for (int nt = 0; nt < 8; nt++)
                        mma_f16(acc[mt][nt], a[mt], &br[nt >> 1][(nt & 1) * 2]);
            }
            __syncwarp();
            if (lane == 0) mbar_arrive(EMPTYB(kc));
        }

        // -------- epilogue: direct fp16 stores + rowmax of the ROUNDED values --------
        __half* Sb = g_S + (size_t)b * NPOS * NPOS;
        int rbase = i0 + wm * 64;
        int cbase = j0 + wn * 64 + (lane & 3) * 2;
        #pragma unroll
        for (int mt = 0; mt < 4; mt++) {
            #pragma unroll
            for (int h = 0; h < 2; h++) {
                int r = rbase + mt * 16 + h * 8 + (lane >> 2);
                float m = -INFINITY;
                #pragma unroll
                for (int nt = 0; nt < 8; nt++) {
                    __half2 hv = __floats2half2_rn(acc[mt][nt][h * 2], acc[mt][nt][h * 2 + 1]);
                    float2 f = __half22float2(hv);
                    m = fmaxf(m, fmaxf(f.x, f.y));
                    *(__half2*)&Sb[(size_t)r * NPOS + cbase + nt * 8] = hv;
                }
                m = fmaxf(m, __shfl_xor_sync(0xffffffffu, m, 1));
                m = fmaxf(m, __shfl_xor_sync(0xffffffffu, m, 2));
                if ((lane & 3) == 0) atomicMaxFloat(&g_rowmax[b * NPOS + r], m);
            }
        }
    }
    #undef ISSUE
    #undef FULLB
    #undef EMPTYB
}

// ---------------- kernel 4: per-row softmax denominator (2 rows per CTA) ----------------
__global__ __launch_bounds__(256) void k_rowsum() {
    int half = threadIdx.x >> 7;            // 0/1: which row of the pair
    int t = threadIdx.x & 127;
    int row = blockIdx.x * 2 + half;        // b*NPOS + i
    int b = row >> 12, i = row & (NPOS - 1);
    float rmax = g_rowmax[row];
    float den  = (1.0f - rmax) + EPS_MIN;
    float beta  = INV_H / den;
    float alpha = INV_H - beta;
    const uint4* Sr = (const uint4*)(g_S + (size_t)b * NPOS * NPOS + (size_t)i * NPOS);
    uint4 u[4];
    #pragma unroll
    for (int k = 0; k < 4; k++) u[k] = Sr[t + k * 128];
    float sum = 0.0f;
    #pragma unroll
    for (int k = 0; k < 4; k++) {
        float2 f0 = __half22float2(*(__half2*)&u[k].x);
        float2 f1 = __half22float2(*(__half2*)&u[k].y);
        float2 f2 = __half22float2(*(__half2*)&u[k].z);
        float2 f3 = __half22float2(*(__half2*)&u[k].w);
        sum += __expf(fmaf(beta, f0.x, alpha)) + __expf(fmaf(beta, f0.y, alpha));
        sum += __expf(fmaf(beta, f1.x, alpha)) + __expf(fmaf(beta, f1.y, alpha));
        sum += __expf(fmaf(beta, f2.x, alpha)) + __expf(fmaf(beta, f2.y, alpha));
        sum += __expf(fmaf(beta, f3.x, alpha)) + __expf(fmaf(beta, f3.y, alpha));
    }
    __shared__ float sh[2][4];
    int lane = t & 31, w = t >> 5;
    #pragma unroll
    for (int o = 16; o; o >>= 1) sum += __shfl_xor_sync(0xffffffffu, sum, o);
    if (lane == 0) sh[half][w] = sum;
    __syncthreads();
    if (t == 0) {
        float s = sh[half][0] + sh[half][1] + sh[half][2] + sh[half][3];
        g_bg[row] = make_float2(beta, alpha - logf(s));
    }
}

// ---------------- kernel 5: column max of (gamma_i + beta_i*S_ij), MLP=4 ----------------
#define ICHUNK 128
__global__ __launch_bounds__(256) void k_colmax() {
    int b = blockIdx.z;
    int jBase = blockIdx.x * 2048;          // 256 threads * 8 cols
    int iBase = blockIdx.y * ICHUNK;
    __shared__ float2 bg[ICHUNK];
    if (threadIdx.x < ICHUNK)
        bg[threadIdx.x] = g_bg[b * NPOS + iBase + threadIdx.x];
    __syncthreads();
    const __half* Sb = g_S + (size_t)b * NPOS * NPOS;
    int j = jBase + threadIdx.x * 8;
    float m[8];
    #pragma unroll
    for (int q = 0; q < 8; q++) m[q] = -INFINITY;
    for (int ii = 0; ii < ICHUNK; ii += 4) {
        uint4 u[4];
        #pragma unroll
        for (int r = 0; r < 4; r++)
            u[r] = *(const uint4*)&Sb[(size_t)(iBase + ii + r) * NPOS + j];
        #pragma unroll
        for (int r = 0; r < 4; r++) {
            float2 be_ga = bg[ii + r];
            float be = be_ga.x, ga = be_ga.y;
            float2 f0 = __half22float2(*(__half2*)&u[r].x);
            float2 f1 = __half22float2(*(__half2*)&u[r].y);
            float2 f2 = __half22float2(*(__half2*)&u[r].z);
            float2 f3 = __half22float2(*(__half2*)&u[r].w);
            m[0] = fmaxf(m[0], fmaf(be, f0.x, ga));
            m[1] = fmaxf(m[1], fmaf(be, f0.y, ga));
            m[2] = fmaxf(m[2], fmaf(be, f1.x, ga));
            m[3] = fmaxf(m[3], fmaf(be, f1.y, ga));
            m[4] = fmaxf(m[4], fmaf(be, f2.x, ga));
            m[5] = fmaxf(m[5], fmaf(be, f2.y, ga));
            m[6] = fmaxf(m[6], fmaf(be, f3.x, ga));
            m[7] = fmaxf(m[7], fmaf(be, f3.y, ga));
        }
    }
    float* cm = g_colmax + b * NPOS + j;
    #pragma unroll
    for (int q = 0; q < 8; q++) atomicMaxFloat(cm + q, m[q]);
}

// ---------------- kernel 6: fused per-batch sum(exp(colmax)) + final output ----------------
__global__ __launch_bounds__(256) void k_cxfinal(float* __restrict__ out) {
    int b = blockIdx.x;
    const float* cm = g_colmax + b * NPOS;
    float s = 0.0f;
    #pragma unroll
    for (int k = 0; k < NPOS / 256; k++)
        s += __expf(cm[threadIdx.x + k * 256]);
    s = blockReduceSum(s);
    if (threadIdx.x == 0) out[b] = -logf(s * (1.0f / NPOS));
}

// ---------------- host: tensormap encode via driver entry point ----------------
typedef CUresult (CUDAAPI *PFN_encodeTiled)(
    CUtensorMap*, CUtensorMapDataType, cuuint32_t, void*,
    const cuuint64_t*, const cuuint64_t*, const cuuint32_t*, const cuuint32_t*,
    CUtensorMapInterleave, CUtensorMapSwizzle, CUtensorMapL2promotion, CUtensorMapFloatOOBfill);

static PFN_encodeTiled get_encoder() {
    static PFN_encodeTiled fn = nullptr;
    if (!fn) {
        cudaDriverEntryPointQueryResult st;
        cudaGetDriverEntryPoint("cuTensorMapEncodeTiled", (void**)&fn,
                                cudaEnableDefault, &st);
    }
    return fn;
}

static void make_map(CUtensorMap* tm, void* ptr, uint32_t boxRows) {
    cuuint64_t dims[2]    = {KP, (cuuint64_t)BATCH * NPOS};
    cuuint64_t strides[1] = {KP * 2};
    cuuint32_t box[2]     = {KCHUNK, boxRows};
    cuuint32_t es[2]      = {1, 1};
    get_encoder()(tm, CU_TENSOR_MAP_DATA_TYPE_FLOAT16, 2, ptr,
                  dims, strides, box, es,
                  CU_TENSOR_MAP_INTERLEAVE_NONE, CU_TENSOR_MAP_SWIZZLE_128B,
                  CU_TENSOR_MAP_L2_PROMOTION_L2_128B, CU_TENSOR_MAP_FLOAT_OOB_FILL_NONE);
}

// ---------------- launch ----------------
extern "C" void kernel_launch(void* const* d_in, const int* in_sizes, int n_in,
                              void* d_out, int out_size) {
    const float* X = (const float*)d_in[0];
    const float* Y = (const float*)d_in[1];
    float* out = (float*)d_out;

    void *pA, *pB;
    cudaGetSymbolAddress(&pA, g_A);
    cudaGetSymbolAddress(&pB, g_Bp);
    CUtensorMap tmA, tmB;
    make_map(&tmA, pA, TILE_M);
    make_map(&tmB, pB, TILE_N);

    static int ncta = 0;
    if (ncta == 0) {
        cudaDeviceProp prop;
        cudaGetDeviceProperties(&prop, 0);
        ncta = prop.multiProcessorCount;
        if (ncta <= 0 || ncta > NT) ncta = 148;
    }

    cudaFuncSetAttribute(k_gemm_tc, cudaFuncAttributeMaxDynamicSharedMemorySize, SMEM_DYN);
    cudaFuncSetAttribute(k_normpack, cudaFuncAttributeMaxDynamicSharedMemorySize, NP_SMEM);

    k_mean<<<BATCH * CH, 256>>>(Y);
    k_normpack<<<dim3(NPOS / 64, BATCH, 2), 256, NP_SMEM>>>(X, Y);
    k_gemm_tc<<<ncta, 256, SMEM_DYN>>>(tmA, tmB, ncta);
    k_rowsum<<<BATCH * NPOS / 2, 256>>>();
    k_colmax<<<dim3(NPOS / 2048, NPOS / ICHUNK, BATCH), 256>>>();
    k_cxfinal<<<BATCH, 256>>>(out);
}